// round 1
// baseline (speedup 1.0000x reference)
#include <cuda_runtime.h>

// DAG fused 1x1-conv layer, fp32, packed f32x2 FMA path.
// B=64, C=64, H*W=1024 -> 65536 positions. 16 GEMMs of [pos x 64 x 64].
//
// Layout:
//   x0,x1 : [64][64][1024]  (b, c, p)
//   W_pre : [2][64][64]     (g, o, c)
//   W_edge: [14][64][64]
//   out   : [64][256][1024] (b, node*64+o, p)
//
// One block = (b, 64-position tile). All 6 DAG states kept in smem,
// stored ReLU'd (edges always consume relu(state)); raw node values are
// written to global directly from registers. Weights are pre-splatted
// ({w,w} float2) and transposed to [g][c][o] once by a prep kernel so the
// main GEMM does packed fma.rn.f32x2 with no shuffles/movs.

#define NG        16      // 2 preproc + 14 edge GEMMs
#define TPOS      64      // positions per tile
#define NTHREADS  128     // 8 o-groups x 16 p-groups
#define SMEM_BYTES (6 * 64 * TPOS * 4)   // 98304

// [g][c][2*o] : splatted weight pairs, 16 * 64 * 128 floats = 512 KB scratch
__device__ __align__(16) float g_wsp[NG * 64 * 128];

__global__ void prep_weights_kernel(const float* __restrict__ Wpre,
                                    const float* __restrict__ Wedge) {
    int idx = blockIdx.x * blockDim.x + threadIdx.x;
    if (idx >= NG * 64 * 64) return;
    int g = idx >> 12;          // GEMM index
    int r = idx & 4095;
    int o = r >> 6;
    int c = r & 63;
    float w = (g < 2) ? Wpre[g * 4096 + o * 64 + c]
                      : Wedge[(g - 2) * 4096 + o * 64 + c];
    float2* dst = reinterpret_cast<float2*>(g_wsp);
    dst[(g * 64 + c) * 64 + o] = make_float2(w, w);
}

__device__ __forceinline__ void ffma2(unsigned long long& d,
                                      unsigned long long a,
                                      unsigned long long b) {
    asm("fma.rn.f32x2 %0, %1, %2, %0;" : "+l"(d) : "l"(a), "l"(b));
}

__device__ __forceinline__ float2 u2f2(unsigned long long v) {
    float2 r;
    asm("mov.b64 {%0, %1}, %2;" : "=f"(r.x), "=f"(r.y) : "l"(v));
    return r;
}

struct Acc { unsigned long long v[8][2]; };  // 8 o x 4 p (2 f32x2)

__device__ __forceinline__ void acc_zero(Acc& A) {
    #pragma unroll
    for (int i = 0; i < 8; ++i) { A.v[i][0] = 0ull; A.v[i][1] = 0ull; }
}

// Accumulate one 64x64 GEMM over a state tile in smem.
// stin: smem [64 c][TPOS p]   wg: g_wsp + g*8192 ([c][128] floats)
__device__ __forceinline__ void gemm_acc(Acc& A,
                                         const float* __restrict__ stin,
                                         const float* __restrict__ wg,
                                         int p, int o0) {
    const float* xp = stin + p;
    const float* wp = wg + o0 * 2;
    #pragma unroll 8
    for (int c = 0; c < 64; ++c) {
        ulonglong2 xv  = *reinterpret_cast<const ulonglong2*>(xp);
        ulonglong2 w01 = *reinterpret_cast<const ulonglong2*>(wp);
        ulonglong2 w23 = *reinterpret_cast<const ulonglong2*>(wp + 4);
        ulonglong2 w45 = *reinterpret_cast<const ulonglong2*>(wp + 8);
        ulonglong2 w67 = *reinterpret_cast<const ulonglong2*>(wp + 12);
        ffma2(A.v[0][0], w01.x, xv.x); ffma2(A.v[0][1], w01.x, xv.y);
        ffma2(A.v[1][0], w01.y, xv.x); ffma2(A.v[1][1], w01.y, xv.y);
        ffma2(A.v[2][0], w23.x, xv.x); ffma2(A.v[2][1], w23.x, xv.y);
        ffma2(A.v[3][0], w23.y, xv.x); ffma2(A.v[3][1], w23.y, xv.y);
        ffma2(A.v[4][0], w45.x, xv.x); ffma2(A.v[4][1], w45.x, xv.y);
        ffma2(A.v[5][0], w45.y, xv.x); ffma2(A.v[5][1], w45.y, xv.y);
        ffma2(A.v[6][0], w67.x, xv.x); ffma2(A.v[6][1], w67.x, xv.y);
        ffma2(A.v[7][0], w67.y, xv.x); ffma2(A.v[7][1], w67.y, xv.y);
        xp += TPOS;
        wp += 128;
    }
}

// Store ReLU'd state to smem only (preproc states).
__device__ __forceinline__ void store_relu_smem(float* sdst, const Acc& A,
                                                int p, int o0) {
    #pragma unroll
    for (int oo = 0; oo < 8; ++oo) {
        float2 a = u2f2(A.v[oo][0]);
        float2 b = u2f2(A.v[oo][1]);
        float4 v = make_float4(fmaxf(a.x, 0.f), fmaxf(a.y, 0.f),
                               fmaxf(b.x, 0.f), fmaxf(b.y, 0.f));
        *reinterpret_cast<float4*>(sdst + (o0 + oo) * TPOS + p) = v;
    }
}

// Node state: raw -> global output, ReLU'd -> smem.
__device__ __forceinline__ void store_node(float* __restrict__ gout,
                                           float* sdst, const Acc& A,
                                           int p, int o0) {
    #pragma unroll
    for (int oo = 0; oo < 8; ++oo) {
        float2 a = u2f2(A.v[oo][0]);
        float2 b = u2f2(A.v[oo][1]);
        *reinterpret_cast<float4*>(gout + (o0 + oo) * 1024 + p) =
            make_float4(a.x, a.y, b.x, b.y);
        *reinterpret_cast<float4*>(sdst + (o0 + oo) * TPOS + p) =
            make_float4(fmaxf(a.x, 0.f), fmaxf(a.y, 0.f),
                        fmaxf(b.x, 0.f), fmaxf(b.y, 0.f));
    }
}

__global__ void __launch_bounds__(NTHREADS, 2)
dag_kernel(const float* __restrict__ x0,
           const float* __restrict__ x1,
           float* __restrict__ out) {
    extern __shared__ float st[];     // [6][64][TPOS]
    const int tid = threadIdx.x;
    const int b   = blockIdx.x >> 4;  // 16 position-tiles per batch image
    const int pt  = blockIdx.x & 15;
    const int p0  = pt * TPOS;

    // --- Stage raw x0 -> slot 4, x1 -> slot 5 (overwritten later by nodes 2,3)
    {
        const float4* gx0 = reinterpret_cast<const float4*>(x0 + b * 65536 + p0);
        const float4* gx1 = reinterpret_cast<const float4*>(x1 + b * 65536 + p0);
        float4* s4 = reinterpret_cast<float4*>(st + 4 * 4096);
        float4* s5 = reinterpret_cast<float4*>(st + 5 * 4096);
        #pragma unroll
        for (int j = 0; j < 8; ++j) {
            int idx = tid + j * NTHREADS;   // 0..1023 = 64 c * 16 q
            int c = idx >> 4;
            int q = idx & 15;
            s4[c * 16 + q] = gx0[c * 256 + q];
            s5[c * 16 + q] = gx1[c * 256 + q];
        }
    }
    __syncthreads();

    const int og = tid >> 4;     // 0..7  -> 8 output channels each
    const int pg = tid & 15;     // 0..15 -> 4 positions each
    const int p  = pg * 4;
    const int o0 = og * 8;

    Acc A;

    // --- Preproc: states 0,1 = conv(x, W_pre) ; store ReLU'd (only ever
    //     consumed through relu; raw preproc states never reach the output)
    acc_zero(A);
    gemm_acc(A, st + 4 * 4096, g_wsp + 0 * 8192, p, o0);
    store_relu_smem(st + 0 * 4096, A, p, o0);
    acc_zero(A);
    gemm_acc(A, st + 5 * 4096, g_wsp + 1 * 8192, p, o0);
    store_relu_smem(st + 1 * 4096, A, p, o0);
    __syncthreads();

    // --- DAG nodes: node i sums conv over all prior (relu'd) states
    int g = 2;
    #pragma unroll 1
    for (int i = 0; i < 4; ++i) {
        acc_zero(A);
        #pragma unroll 1
        for (int s = 0; s < 2 + i; ++s)
            gemm_acc(A, st + s * 4096, g_wsp + (g + s) * 8192, p, o0);
        g += 2 + i;
        store_node(out + b * 262144 + i * 65536 + p0,
                   st + (2 + i) * 4096, A, p, o0);
        __syncthreads();
    }
}

extern "C" void kernel_launch(void* const* d_in, const int* in_sizes, int n_in,
                              void* d_out, int out_size) {
    const float* x0    = (const float*)d_in[0];
    const float* x1    = (const float*)d_in[1];
    const float* Wpre  = (const float*)d_in[2];
    const float* Wedge = (const float*)d_in[3];
    float* out = (float*)d_out;

    // Splat + transpose all 16 weight matrices into device scratch.
    prep_weights_kernel<<<256, 256>>>(Wpre, Wedge);

    cudaFuncSetAttribute(dag_kernel,
                         cudaFuncAttributeMaxDynamicSharedMemorySize,
                         SMEM_BYTES);
    dag_kernel<<<64 * 16, NTHREADS, SMEM_BYTES>>>(x0, x1, out);
}